// round 6
// baseline (speedup 1.0000x reference)
#include <cuda_runtime.h>
#include <cuda_fp16.h>

// Problem constants
#define NN    25000
#define NPAD  25024          // multiple of 64; NPAD*16 == 1564*256 exactly
#define EE    400000
#define FN    32
#define FE    16
#define HH    16
#define MM    16
#define MPITERS 3

// ---------------- scratch (device globals) ---------------------------------
__device__ float  g_hidden [NPAD * HH];
__device__ float  g_hidden0[NPAD * HH];
__device__ __half g_Th     [NPAD * FE * MM];  // T2[n][m*16+f], fp16, 512B/node
__device__ float  g_bb     [NPAD * MM];
__device__ float  g_msg    [NPAD * MM];
__device__ int    g_count  [NPAD];            // invariant: 0 at kernel_launch entry
__device__ int    g_cursor [NPAD];
__device__ int4   g_pack   [EE];              // {orig_e, sender, receiver, 0} sender-sorted

// ---------------- f32x2 helpers -------------------------------------------
__device__ __forceinline__ unsigned long long pk2(float lo, float hi) {
    unsigned long long d;
    asm("mov.b64 %0, {%1, %2};" : "=l"(d) : "r"(__float_as_uint(lo)), "r"(__float_as_uint(hi)));
    return d;
}
__device__ __forceinline__ unsigned long long fma2(unsigned long long a,
                                                   unsigned long long b,
                                                   unsigned long long c) {
    unsigned long long d;
    asm("fma.rn.f32x2 %0, %1, %2, %3;" : "=l"(d) : "l"(a), "l"(b), "l"(c));
    return d;
}
__device__ __forceinline__ float upk_sum(unsigned long long v) {
    unsigned int a, b;
    asm("mov.b64 {%0, %1}, %2;" : "=r"(a), "=r"(b) : "l"(v));
    return __uint_as_float(a) + __uint_as_float(b);
}
__device__ __forceinline__ float tanh_fast(float x) {
    float r;
    asm("tanh.approx.f32 %0, %1;" : "=f"(r) : "f"(x));
    return r;
}
__device__ __forceinline__ float sigmoid_fast(float x) {
    return fmaf(0.5f, tanh_fast(0.5f * x), 0.5f);
}
__device__ __forceinline__ float dot4(float4 a, float4 b) {
    float r = a.x * b.x;
    r = fmaf(a.y, b.y, r);
    r = fmaf(a.z, b.z, r);
    r = fmaf(a.w, b.w, r);
    return r;
}

// ---------------- kernel 1: init hidden + hist + zero msg/out --------------
__global__ __launch_bounds__(256)
void init_kernel(const float* __restrict__ nf, const float* __restrict__ Wi,
                 const float* __restrict__ bi, const int* __restrict__ send,
                 float* __restrict__ out) {
    __shared__ float Wsh[FN * HH];
    int tid = threadIdx.x;
    int gid = blockIdx.x * 256 + tid;

    if (gid < EE) atomicAdd(&g_count[send[gid]], 1);   // g_count==0 at entry
    g_msg[gid] = 0.f;                                   // grid*256 == NPAD*16
    if (gid == 0) out[0] = 0.f;

    int j  = tid & 15;
    int nl = tid >> 4;
    int n  = blockIdx.x * 16 + nl;
    for (int idx = tid; idx < FN * HH; idx += 256) Wsh[idx] = Wi[idx];
    __syncthreads();

    int nr = (n < NN) ? n : (NN - 1);
    const float* row = nf + (long)nr * FN;
    float acc = bi[j];
#pragma unroll
    for (int f = 0; f < FN; f++) acc = fmaf(row[f], Wsh[f * 16 + j], acc);
    g_hidden [n * 16 + j] = acc;
    g_hidden0[n * 16 + j] = acc;
}

// ---------------- scan: cursor = exclusive prefix; re-zero count -----------
__global__ __launch_bounds__(1024)
void scan_kernel() {
    __shared__ int sh[1024];
    int t = threadIdx.x;
    int vals[25];
    int sum = 0;
    int base = t * 25;
#pragma unroll
    for (int k = 0; k < 25; k++) {
        int idx = base + k;
        int v = (idx < NPAD) ? g_count[idx] : 0;
        vals[k] = v; sum += v;
    }
    sh[t] = sum;
    __syncthreads();
    for (int off = 1; off < 1024; off <<= 1) {
        int v = (t >= off) ? sh[t - off] : 0;
        __syncthreads();
        sh[t] += v;
        __syncthreads();
    }
    int ex = (t == 0) ? 0 : sh[t - 1];
#pragma unroll
    for (int k = 0; k < 25; k++) {
        int idx = base + k;
        if (idx < NPAD) { g_cursor[idx] = ex; ex += vals[k]; g_count[idx] = 0; }
    }
}

// ---------------- scatter: build sorted packed edge records ----------------
__global__ __launch_bounds__(256)
void scatter_kernel(const int* __restrict__ send, const int* __restrict__ recv) {
    int e = blockIdx.x * 256 + threadIdx.x;
    if (e < EE) {
        int s = send[e];
        int r = recv[e];
        int p = atomicAdd(&g_cursor[s], 1);
        g_pack[p] = make_int4(e, s, r, 0);
    }
}

// ---------------- kernel 2: per-node T (fp16, transposed) / bb -------------
// thread = (m2 = tid>>4, f2 = tid&15); W column register-resident; 64 nodes
// staged in shared per block.
__global__ __launch_bounds__(256)
void t_kernel(const float* __restrict__ We, const float* __restrict__ be) {
    __shared__ __align__(16) float sh[64 * HH];
    int tid = threadIdx.x;
    int f2 = tid & 15;
    int m2 = tid >> 4;

    const float4* wp4 = (const float4*)(We + (f2 * 256 + m2 * 16));
    float4 w0 = wp4[0], w1 = wp4[1], w2 = wp4[2], w3 = wp4[3];
    float4 b0 = make_float4(0, 0, 0, 0), b1 = b0, b2 = b0, b3 = b0;
    if (f2 == 0) {
        const float4* bp = (const float4*)(be + m2 * 16);
        b0 = bp[0]; b1 = bp[1]; b2 = bp[2]; b3 = bp[3];
    }

    int base = blockIdx.x * 64;
    int cnt = NN - base;
    if (cnt > 64) cnt = 64;
    if (cnt <= 0) return;

    for (int idx = tid; idx < cnt * HH; idx += 256)
        sh[idx] = g_hidden[base * HH + idx];
    __syncthreads();

#pragma unroll 2
    for (int nl = 0; nl < cnt; nl++) {
        const float4* hp = (const float4*)(sh + nl * HH);
        float4 h0 = hp[0], h1 = hp[1], h2 = hp[2], h3 = hp[3];
        float acc = dot4(w0, h0) + dot4(w1, h1) + dot4(w2, h2) + dot4(w3, h3);
        g_Th[(long)(base + nl) * 256 + tid] = __float2half_rn(acc);
        if (f2 == 0) {
            g_bb[(base + nl) * 16 + m2] =
                dot4(b0, h0) + dot4(b1, h1) + dot4(b2, h2) + dot4(b3, h3);
        }
    }
}

// ---------------- kernel 3: per-edge message (fp16 T, batched) -------------
// 4 threads/edge; mg owns m = mg*4..mg*4+3. 8 LDG.128 of T issued up front.
__global__ __launch_bounds__(256)
void edge_kernel(const float* __restrict__ ef) {
    int tid = threadIdx.x;
    int i  = blockIdx.x * 64 + (tid >> 2);
    int mg = tid & 3;

    int4 pk = g_pack[i];
    int e = pk.x, s = pk.y, r = pk.z;

    const float4* ep = (const float4*)(ef + (long)e * 16);
    float4 e0 = ep[0], e1 = ep[1], e2 = ep[2], e3 = ep[3];

    const uint4* tp = (const uint4*)(g_Th + (long)s * 256);
    uint4 tv[8];
#pragma unroll
    for (int q = 0; q < 4; q++) {
        tv[q * 2]     = tp[(mg * 4 + q) * 2];
        tv[q * 2 + 1] = tp[(mg * 4 + q) * 2 + 1];
    }
    float4 bbv = *(const float4*)(g_bb + s * 16 + mg * 4);
    float bbs[4] = {bbv.x, bbv.y, bbv.z, bbv.w};

    float w[16] = {e0.x, e0.y, e0.z, e0.w, e1.x, e1.y, e1.z, e1.w,
                   e2.x, e2.y, e2.z, e2.w, e3.x, e3.y, e3.z, e3.w};
    unsigned long long wp[8];
#pragma unroll
    for (int k = 0; k < 8; k++) wp[k] = pk2(w[2 * k], w[2 * k + 1]);

    float outv[4];
#pragma unroll
    for (int q = 0; q < 4; q++) {
        unsigned long long acc = pk2(bbs[q], 0.f);
        const __half2* hh = (const __half2*)&tv[q * 2];
#pragma unroll
        for (int k = 0; k < 8; k++) {
            float2 v = __half22float2(hh[k]);
            acc = fma2(pk2(v.x, v.y), wp[k], acc);
        }
        outv[q] = upk_sum(acc);
    }
    float* dst = g_msg + r * 16 + mg * 4;
    asm volatile("red.global.add.v4.f32 [%0], {%1, %2, %3, %4};"
                 :: "l"(dst), "f"(outv[0]), "f"(outv[1]), "f"(outv[2]), "f"(outv[3])
                 : "memory");
}

// ---------------- kernel 4: GRU, 4 nodes per thread ------------------------
__global__ __launch_bounds__(256)
void gru_kernel(const float* __restrict__ Wi, const float* __restrict__ Wh,
                const float* __restrict__ bi, const float* __restrict__ bh) {
    __shared__ __align__(16) float sh_h[2][64][16];
    __shared__ float sh_seq[64][33];

    int tid = threadIdx.x;
    int j  = tid & 15;
    int sl = tid >> 4;
    int nbase = blockIdx.x * 64;

    unsigned long long wz[8], wr[8], wh[8];
#pragma unroll
    for (int k = 0; k < 8; k++) {
        wz[k] = pk2(Wh[(2 * k) * 48 + j],      Wh[(2 * k + 1) * 48 + j]);
        wr[k] = pk2(Wh[(2 * k) * 48 + 16 + j], Wh[(2 * k + 1) * 48 + 16 + j]);
        wh[k] = pk2(Wh[(2 * k) * 48 + 32 + j], Wh[(2 * k + 1) * 48 + 32 + j]);
    }
    float wiz = Wi[j], wir = Wi[16 + j], wih = Wi[32 + j];
    float biz = bi[j], bir = bi[16 + j], bih = bi[32 + j];
    float bhz = bh[j], bhr = bh[16 + j], bhh = bh[32 + j];

    float h[4];
#pragma unroll
    for (int u = 0; u < 4; u++) {
        int row = sl + u * 16;
        int n = nbase + row;
        sh_seq[row][j]      = g_hidden[n * 16 + j];
        sh_seq[row][16 + j] = g_msg   [n * 16 + j];
        g_msg[n * 16 + j] = 0.f;          // re-zero for next iteration's edge pass
        sh_h[0][row][j] = 0.f;
        h[u] = 0.f;
    }
    __syncthreads();

#pragma unroll 1
    for (int t = 0; t < 32; t++) {
        int cur = t & 1;
        float x[4];
        unsigned long long az[4], ar[4], ah[4];
#pragma unroll
        for (int u = 0; u < 4; u++) {
            x[u] = sh_seq[sl + u * 16][t];
            az[u] = pk2(bhz, 0.f);
            ar[u] = pk2(bhr, 0.f);
            ah[u] = pk2(bhh, 0.f);
        }
#pragma unroll
        for (int k = 0; k < 4; k++) {
#pragma unroll
            for (int u = 0; u < 4; u++) {
                ulonglong2 p = ((const ulonglong2*)sh_h[cur][sl + u * 16])[k];
                az[u] = fma2(p.x, wz[2 * k],     az[u]);
                az[u] = fma2(p.y, wz[2 * k + 1], az[u]);
                ar[u] = fma2(p.x, wr[2 * k],     ar[u]);
                ar[u] = fma2(p.y, wr[2 * k + 1], ar[u]);
                ah[u] = fma2(p.x, wh[2 * k],     ah[u]);
                ah[u] = fma2(p.y, wh[2 * k + 1], ah[u]);
            }
        }
#pragma unroll
        for (int u = 0; u < 4; u++) {
            float ghz = upk_sum(az[u]), ghr = upk_sum(ar[u]), ghh = upk_sum(ah[u]);
            float z = sigmoid_fast(fmaf(x[u], wiz, biz) + ghz);
            float r = sigmoid_fast(fmaf(x[u], wir, bir) + ghr);
            float hc = tanh_fast(fmaf(x[u], wih, bih) + r * ghh);
            h[u] = hc + z * (h[u] - hc);
            sh_h[cur ^ 1][sl + u * 16][j] = h[u];
        }
        __syncwarp();
    }
#pragma unroll
    for (int u = 0; u < 4; u++)
        g_hidden[(nbase + sl + u * 16) * 16 + j] = h[u];
}

// ---------------- readout --------------------------------------------------
__global__ __launch_bounds__(256)
void readout_kernel(const float* __restrict__ Wri, const float* __restrict__ bri,
                    const float* __restrict__ Wrj, const float* __restrict__ brj,
                    float* __restrict__ out) {
    int n = blockIdx.x * 256 + threadIdx.x;
    float p = 0.f;
    if (n < NN) {
        const float4* hp  = (const float4*)(g_hidden  + n * 16);
        const float4* h0p = (const float4*)(g_hidden0 + n * 16);
        const float4* wi  = (const float4*)Wri;
        const float4* wj  = (const float4*)Wrj;
        float4 h0 = hp[0], h1 = hp[1], h2 = hp[2], h3 = hp[3];
        float4 g0 = h0p[0], g1 = h0p[1], g2 = h0p[2], g3 = h0p[3];
        float iv = bri[0]
                 + dot4(h0, wi[0]) + dot4(h1, wi[1]) + dot4(h2, wi[2]) + dot4(h3, wi[3])
                 + dot4(g0, wi[4]) + dot4(g1, wi[5]) + dot4(g2, wi[6]) + dot4(g3, wi[7]);
        float jv = brj[0]
                 + dot4(h0, wj[0]) + dot4(h1, wj[1]) + dot4(h2, wj[2]) + dot4(h3, wj[3]);
        p = iv * jv;
    }
#pragma unroll
    for (int off = 16; off > 0; off >>= 1)
        p += __shfl_down_sync(0xffffffffu, p, off);
    if ((threadIdx.x & 31) == 0) atomicAdd(out, p);
}

// ---------------- launch ---------------------------------------------------
extern "C" void kernel_launch(void* const* d_in, const int* in_sizes, int n_in,
                              void* d_out, int out_size) {
    const float* nf     = (const float*)d_in[0];
    const float* ef     = (const float*)d_in[1];
    const float* W_init = (const float*)d_in[2];
    const float* b_init = (const float*)d_in[3];
    const float* W_edge = (const float*)d_in[4];
    const float* b_edge = (const float*)d_in[5];
    const float* Wi_gru = (const float*)d_in[6];
    const float* Wh_gru = (const float*)d_in[7];
    const float* bi_gru = (const float*)d_in[8];
    const float* bh_gru = (const float*)d_in[9];
    const float* W_ri   = (const float*)d_in[10];
    const float* b_ri   = (const float*)d_in[11];
    const float* W_rj   = (const float*)d_in[12];
    const float* b_rj   = (const float*)d_in[13];
    const int*   recv   = (const int*)d_in[14];
    const int*   send   = (const int*)d_in[15];
    float* out = (float*)d_out;

    init_kernel<<<NPAD / 16, 256>>>(nf, W_init, b_init, send, out);
    scan_kernel<<<1, 1024>>>();
    scatter_kernel<<<(EE + 255) / 256, 256>>>(send, recv);

    for (int it = 0; it < MPITERS; it++) {
        t_kernel<<<(NN + 63) / 64, 256>>>(W_edge, b_edge);
        edge_kernel<<<EE / 64, 256>>>(ef);
        gru_kernel<<<NPAD / 64, 256>>>(Wi_gru, Wh_gru, bi_gru, bh_gru);
    }

    readout_kernel<<<(NN + 255) / 256, 256>>>(W_ri, b_ri, W_rj, b_rj, out);
}

// round 7
// speedup vs baseline: 1.0689x; 1.0689x over previous
#include <cuda_runtime.h>
#include <cuda_fp16.h>
#include <mma.h>
using namespace nvcuda;

// Problem constants
#define NN    25000
#define NPAD  25024          // multiple of 64; NPAD*16 == 1564*256 exactly
#define EE    400000
#define FN    32
#define FE    16
#define HH    16
#define MM    16
#define MPITERS 3

// ---------------- scratch (device globals) ---------------------------------
__device__ float  g_hidden [NPAD * HH];
__device__ float  g_hidden0[NPAD * HH];
__device__ __half g_Th     [NPAD * FE * MM];  // T2[n][m*16+f], fp16, 512B/node
__device__ float  g_bb     [NPAD * MM];
__device__ float  g_msg    [NPAD * MM];
__device__ __half g_B16    [16 * 272];        // B[h][c]: c<256 -> (m=c>>4,f=c&15): We[f][m*16+h]; c>=256 -> be[(c-256)*16+h]
__device__ int    g_count  [NPAD];            // invariant: 0 at kernel_launch entry
__device__ int    g_cursor [NPAD];
__device__ int4   g_pack   [EE];              // {orig_e, sender, receiver, 0} sender-sorted

// ---------------- f32x2 helpers -------------------------------------------
__device__ __forceinline__ unsigned long long pk2(float lo, float hi) {
    unsigned long long d;
    asm("mov.b64 %0, {%1, %2};" : "=l"(d) : "r"(__float_as_uint(lo)), "r"(__float_as_uint(hi)));
    return d;
}
__device__ __forceinline__ unsigned long long fma2(unsigned long long a,
                                                   unsigned long long b,
                                                   unsigned long long c) {
    unsigned long long d;
    asm("fma.rn.f32x2 %0, %1, %2, %3;" : "=l"(d) : "l"(a), "l"(b), "l"(c));
    return d;
}
__device__ __forceinline__ float upk_sum(unsigned long long v) {
    unsigned int a, b;
    asm("mov.b64 {%0, %1}, %2;" : "=r"(a), "=r"(b) : "l"(v));
    return __uint_as_float(a) + __uint_as_float(b);
}
__device__ __forceinline__ float tanh_fast(float x) {
    float r;
    asm("tanh.approx.f32 %0, %1;" : "=f"(r) : "f"(x));
    return r;
}
__device__ __forceinline__ float sigmoid_fast(float x) {
    return fmaf(0.5f, tanh_fast(0.5f * x), 0.5f);
}
__device__ __forceinline__ float dot4(float4 a, float4 b) {
    float r = a.x * b.x;
    r = fmaf(a.y, b.y, r);
    r = fmaf(a.z, b.z, r);
    r = fmaf(a.w, b.w, r);
    return r;
}

// ---------------- kernel 1: init hidden + hist + zero msg/out --------------
__global__ __launch_bounds__(256)
void init_kernel(const float* __restrict__ nf, const float* __restrict__ Wi,
                 const float* __restrict__ bi, const int* __restrict__ send,
                 float* __restrict__ out) {
    __shared__ float Wsh[FN * HH];
    int tid = threadIdx.x;
    int gid = blockIdx.x * 256 + tid;

    if (gid < EE) atomicAdd(&g_count[send[gid]], 1);   // g_count==0 at entry
    g_msg[gid] = 0.f;                                   // grid*256 == NPAD*16
    if (gid == 0) out[0] = 0.f;

    int j  = tid & 15;
    int nl = tid >> 4;
    int n  = blockIdx.x * 16 + nl;
    for (int idx = tid; idx < FN * HH; idx += 256) Wsh[idx] = Wi[idx];
    __syncthreads();

    int nr = (n < NN) ? n : (NN - 1);
    const float* row = nf + (long)nr * FN;
    float acc = bi[j];
#pragma unroll
    for (int f = 0; f < FN; f++) acc = fmaf(row[f], Wsh[f * 16 + j], acc);
    g_hidden [n * 16 + j] = acc;
    g_hidden0[n * 16 + j] = acc;
}

// ---------------- scan: prefix sum + re-zero count + build B16 -------------
__global__ __launch_bounds__(1024)
void scan_kernel(const float* __restrict__ We, const float* __restrict__ be) {
    __shared__ int sh[1024];
    int t = threadIdx.x;

    // build fp16 B matrix for the T GEMM (independent of scan data)
    for (int idx = t; idx < 16 * 272; idx += 1024) {
        int h = idx / 272, c = idx % 272;
        float v = (c < 256) ? We[(c & 15) * 256 + (c >> 4) * 16 + h]
                            : be[(c - 256) * 16 + h];
        g_B16[idx] = __float2half_rn(v);
    }

    int vals[25];
    int sum = 0;
    int base = t * 25;
#pragma unroll
    for (int k = 0; k < 25; k++) {
        int idx = base + k;
        int v = (idx < NPAD) ? g_count[idx] : 0;
        vals[k] = v; sum += v;
    }
    sh[t] = sum;
    __syncthreads();
    for (int off = 1; off < 1024; off <<= 1) {
        int v = (t >= off) ? sh[t - off] : 0;
        __syncthreads();
        sh[t] += v;
        __syncthreads();
    }
    int ex = (t == 0) ? 0 : sh[t - 1];
#pragma unroll
    for (int k = 0; k < 25; k++) {
        int idx = base + k;
        if (idx < NPAD) { g_cursor[idx] = ex; ex += vals[k]; g_count[idx] = 0; }
    }
}

// ---------------- scatter: build sorted packed edge records ----------------
__global__ __launch_bounds__(256)
void scatter_kernel(const int* __restrict__ send, const int* __restrict__ recv) {
    int e = blockIdx.x * 256 + threadIdx.x;
    if (e < EE) {
        int s = send[e];
        int r = recv[e];
        int p = atomicAdd(&g_cursor[s], 1);
        g_pack[p] = make_int4(e, s, r, 0);
    }
}

// ---------------- kernel 2: T/bb via tensor cores (wmma) -------------------
// 4 warps/block, each warp = one 16-node tile. A = h tile (fp16, from
// g_hidden), B = g_B16 [16 x 272]. 17 mmas/warp. T rows written as 512B
// vector stores; bb (cols 256..271) written fp32.
__global__ __launch_bounds__(128)
void t_mma_kernel() {
    __shared__ __half shA[4][16][16];
    __shared__ __half shC[4][16][272];
    __shared__ float  shT[4][16][16];

    int w = threadIdx.x >> 5, lane = threadIdx.x & 31;
    int nbase = blockIdx.x * 64 + w * 16;

    for (int idx = lane; idx < 256; idx += 32)
        shA[w][idx >> 4][idx & 15] =
            __float2half_rn(g_hidden[(nbase + (idx >> 4)) * 16 + (idx & 15)]);
    __syncwarp();

    wmma::fragment<wmma::matrix_a, 16, 16, 16, __half, wmma::row_major> fa;
    wmma::load_matrix_sync(fa, &shA[w][0][0], 16);

#pragma unroll 1
    for (int j = 0; j < 17; j++) {
        wmma::fragment<wmma::matrix_b, 16, 16, 16, __half, wmma::row_major> fb;
        wmma::load_matrix_sync(fb, g_B16 + j * 16, 272);
        wmma::fragment<wmma::accumulator, 16, 16, 16, float> fc;
        wmma::fill_fragment(fc, 0.f);
        wmma::mma_sync(fc, fa, fb, fc);
        wmma::store_matrix_sync(&shT[w][0][0], fc, 16, wmma::mem_row_major);
        __syncwarp();
        if (j < 16) {
            for (int idx = lane; idx < 256; idx += 32)
                shC[w][idx >> 4][j * 16 + (idx & 15)] =
                    __float2half_rn(shT[w][idx >> 4][idx & 15]);
        } else {
            for (int idx = lane; idx < 256; idx += 32)
                g_bb[(nbase + (idx >> 4)) * 16 + (idx & 15)] =
                    shT[w][idx >> 4][idx & 15];
        }
        __syncwarp();
    }

    // write T rows: 16 nodes x 512B contiguous
    for (int idx = lane; idx < 512; idx += 32) {
        int nl = idx >> 5, c = idx & 31;
        ((uint4*)(g_Th + (long)(nbase + nl) * 256))[c] =
            ((const uint4*)&shC[w][nl][0])[c];
    }
}

// ---------------- kernel 3: per-edge message (fp16 T, staged ef) -----------
// 64 edges/block, 4 threads/edge. pack + ef staged through shared:
// 1 LDG.128 of ef per thread (coalesced 64B rows) instead of 4.
__global__ __launch_bounds__(256)
void edge_kernel(const float* __restrict__ ef) {
    __shared__ int4 shPack[64];
    __shared__ __align__(16) float shEf[64][20];   // stride 80B: conflict-free

    int tid = threadIdx.x;
    int base = blockIdx.x * 64;
    if (tid < 64) shPack[tid] = g_pack[base + tid];
    __syncthreads();

    int le = tid >> 2, q = tid & 3;
    int e = shPack[le].x;
    ((float4*)shEf[le])[q] = ((const float4*)(ef + (long)e * 16))[q];
    int s = shPack[le].y;
    int r = shPack[le].z;
    int mg = q;

    // batched T loads (MLP) while ef staging completes
    const uint4* tp = (const uint4*)(g_Th + (long)s * 256);
    uint4 tv[8];
#pragma unroll
    for (int qq = 0; qq < 4; qq++) {
        tv[qq * 2]     = tp[(mg * 4 + qq) * 2];
        tv[qq * 2 + 1] = tp[(mg * 4 + qq) * 2 + 1];
    }
    float4 bbv = *(const float4*)(g_bb + s * 16 + mg * 4);
    float bbs[4] = {bbv.x, bbv.y, bbv.z, bbv.w};
    __syncthreads();

    unsigned long long wp[8];
#pragma unroll
    for (int k = 0; k < 8; k++)
        wp[k] = pk2(shEf[le][2 * k], shEf[le][2 * k + 1]);

    float outv[4];
#pragma unroll
    for (int qq = 0; qq < 4; qq++) {
        unsigned long long acc = pk2(bbs[qq], 0.f);
        const __half2* hh = (const __half2*)&tv[qq * 2];
#pragma unroll
        for (int k = 0; k < 8; k++) {
            float2 v = __half22float2(hh[k]);
            acc = fma2(pk2(v.x, v.y), wp[k], acc);
        }
        outv[qq] = upk_sum(acc);
    }
    float* dst = g_msg + r * 16 + mg * 4;
    asm volatile("red.global.add.v4.f32 [%0], {%1, %2, %3, %4};"
                 :: "l"(dst), "f"(outv[0]), "f"(outv[1]), "f"(outv[2]), "f"(outv[3])
                 : "memory");
}

// ---------------- kernel 4: GRU, 4 nodes per thread ------------------------
__global__ __launch_bounds__(256)
void gru_kernel(const float* __restrict__ Wi, const float* __restrict__ Wh,
                const float* __restrict__ bi, const float* __restrict__ bh) {
    __shared__ __align__(16) float sh_h[2][64][16];
    __shared__ float sh_seq[64][33];

    int tid = threadIdx.x;
    int j  = tid & 15;
    int sl = tid >> 4;
    int nbase = blockIdx.x * 64;

    unsigned long long wz[8], wr[8], wh[8];
#pragma unroll
    for (int k = 0; k < 8; k++) {
        wz[k] = pk2(Wh[(2 * k) * 48 + j],      Wh[(2 * k + 1) * 48 + j]);
        wr[k] = pk2(Wh[(2 * k) * 48 + 16 + j], Wh[(2 * k + 1) * 48 + 16 + j]);
        wh[k] = pk2(Wh[(2 * k) * 48 + 32 + j], Wh[(2 * k + 1) * 48 + 32 + j]);
    }
    float wiz = Wi[j], wir = Wi[16 + j], wih = Wi[32 + j];
    float biz = bi[j], bir = bi[16 + j], bih = bi[32 + j];
    float bhz = bh[j], bhr = bh[16 + j], bhh = bh[32 + j];

    float h[4];
#pragma unroll
    for (int u = 0; u < 4; u++) {
        int row = sl + u * 16;
        int n = nbase + row;
        sh_seq[row][j]      = g_hidden[n * 16 + j];
        sh_seq[row][16 + j] = g_msg   [n * 16 + j];
        g_msg[n * 16 + j] = 0.f;          // re-zero for next iteration
        sh_h[0][row][j] = 0.f;
        h[u] = 0.f;
    }
    __syncthreads();

#pragma unroll 1
    for (int t = 0; t < 32; t++) {
        int cur = t & 1;
        float x[4];
        unsigned long long az[4], ar[4], ah[4];
#pragma unroll
        for (int u = 0; u < 4; u++) {
            x[u] = sh_seq[sl + u * 16][t];
            az[u] = pk2(bhz, 0.f);
            ar[u] = pk2(bhr, 0.f);
            ah[u] = pk2(bhh, 0.f);
        }
#pragma unroll
        for (int k = 0; k < 4; k++) {
#pragma unroll
            for (int u = 0; u < 4; u++) {
                ulonglong2 p = ((const ulonglong2*)sh_h[cur][sl + u * 16])[k];
                az[u] = fma2(p.x, wz[2 * k],     az[u]);
                az[u] = fma2(p.y, wz[2 * k + 1], az[u]);
                ar[u] = fma2(p.x, wr[2 * k],     ar[u]);
                ar[u] = fma2(p.y, wr[2 * k + 1], ar[u]);
                ah[u] = fma2(p.x, wh[2 * k],     ah[u]);
                ah[u] = fma2(p.y, wh[2 * k + 1], ah[u]);
            }
        }
#pragma unroll
        for (int u = 0; u < 4; u++) {
            float ghz = upk_sum(az[u]), ghr = upk_sum(ar[u]), ghh = upk_sum(ah[u]);
            float z = sigmoid_fast(fmaf(x[u], wiz, biz) + ghz);
            float r = sigmoid_fast(fmaf(x[u], wir, bir) + ghr);
            float hc = tanh_fast(fmaf(x[u], wih, bih) + r * ghh);
            h[u] = hc + z * (h[u] - hc);
            sh_h[cur ^ 1][sl + u * 16][j] = h[u];
        }
        __syncwarp();
    }
#pragma unroll
    for (int u = 0; u < 4; u++)
        g_hidden[(nbase + sl + u * 16) * 16 + j] = h[u];
}

// ---------------- readout --------------------------------------------------
__global__ __launch_bounds__(256)
void readout_kernel(const float* __restrict__ Wri, const float* __restrict__ bri,
                    const float* __restrict__ Wrj, const float* __restrict__ brj,
                    float* __restrict__ out) {
    int n = blockIdx.x * 256 + threadIdx.x;
    float p = 0.f;
    if (n < NN) {
        const float4* hp  = (const float4*)(g_hidden  + n * 16);
        const float4* h0p = (const float4*)(g_hidden0 + n * 16);
        const float4* wi  = (const float4*)Wri;
        const float4* wj  = (const float4*)Wrj;
        float4 h0 = hp[0], h1 = hp[1], h2 = hp[2], h3 = hp[3];
        float4 g0 = h0p[0], g1 = h0p[1], g2 = h0p[2], g3 = h0p[3];
        float iv = bri[0]
                 + dot4(h0, wi[0]) + dot4(h1, wi[1]) + dot4(h2, wi[2]) + dot4(h3, wi[3])
                 + dot4(g0, wi[4]) + dot4(g1, wi[5]) + dot4(g2, wi[6]) + dot4(g3, wi[7]);
        float jv = brj[0]
                 + dot4(h0, wj[0]) + dot4(h1, wj[1]) + dot4(h2, wj[2]) + dot4(h3, wj[3]);
        p = iv * jv;
    }
#pragma unroll
    for (int off = 16; off > 0; off >>= 1)
        p += __shfl_down_sync(0xffffffffu, p, off);
    if ((threadIdx.x & 31) == 0) atomicAdd(out, p);
}

// ---------------- launch ---------------------------------------------------
extern "C" void kernel_launch(void* const* d_in, const int* in_sizes, int n_in,
                              void* d_out, int out_size) {
    const float* nf     = (const float*)d_in[0];
    const float* ef     = (const float*)d_in[1];
    const float* W_init = (const float*)d_in[2];
    const float* b_init = (const float*)d_in[3];
    const float* W_edge = (const float*)d_in[4];
    const float* b_edge = (const float*)d_in[5];
    const float* Wi_gru = (const float*)d_in[6];
    const float* Wh_gru = (const float*)d_in[7];
    const float* bi_gru = (const float*)d_in[8];
    const float* bh_gru = (const float*)d_in[9];
    const float* W_ri   = (const float*)d_in[10];
    const float* b_ri   = (const float*)d_in[11];
    const float* W_rj   = (const float*)d_in[12];
    const float* b_rj   = (const float*)d_in[13];
    const int*   recv   = (const int*)d_in[14];
    const int*   send   = (const int*)d_in[15];
    float* out = (float*)d_out;

    init_kernel<<<NPAD / 16, 256>>>(nf, W_init, b_init, send, out);
    scan_kernel<<<1, 1024>>>(W_edge, b_edge);
    scatter_kernel<<<(EE + 255) / 256, 256>>>(send, recv);

    for (int it = 0; it < MPITERS; it++) {
        t_mma_kernel<<<NPAD / 64, 128>>>();
        edge_kernel<<<EE / 64, 256>>>(ef);
        gru_kernel<<<NPAD / 64, 256>>>(Wi_gru, Wh_gru, bi_gru, bh_gru);
    }

    readout_kernel<<<(NN + 255) / 256, 256>>>(W_ri, b_ri, W_rj, b_rj, out);
}